// round 15
// baseline (speedup 1.0000x reference)
#include <cuda_runtime.h>
#include <cstddef>
#include <cstdint>

// Problem constants
#define BATCH   2048
#define NTOK    98
#define EMB     192
#define NHEADS  6
#define HDIM    32
#define NWIN    64
#define NN      (NTOK*NTOK)        // 9604
#define NCP     112                // padded key/col dim for attention tiles
#define NNP     (NTOK*NCP)         // 10976 padded bm row block
#define MROWS   (BATCH*NTOK)       // 200704
#define VTP     112                // V^T global token stride (= NCP, covers all staged tokens)
#define SVSTR   136                // V^T smem row stride (>=112, 136 % 32 == 8 -> conflict-free)

// Scratch (device globals — no allocation allowed)
__device__ float d_qkv[(size_t)BATCH * 3 * NHEADS * NTOK * HDIM];   // tf32-rounded Q,K; V slot unused
__device__ float d_vt[(size_t)BATCH * NHEADS * HDIM * VTP];         // tf32-rounded V^T [b][h][d][n_pad] (pads stay 0)
__device__ float d_attnout[(size_t)BATCH * NTOK * EMB];             // tf32-rounded [b][n][h*32+d]
__device__ float d_bm[(size_t)NHEADS * NWIN * NNP];                 // bias+mask fp32, padded cols
__device__ float d_xt[(size_t)MROWS * EMB];                         // tf32-rounded x
__device__ float d_wq[3 * EMB * EMB];                               // tf32-rounded qkv_w
__device__ float d_wo[EMB * EMB];                                   // tf32-rounded o_w

// ---------------------------------------------------------------------------
// helpers
// ---------------------------------------------------------------------------
__device__ __forceinline__ uint32_t f2tf32(float f) {
    uint32_t u;
    asm("cvt.rna.tf32.f32 %0, %1;" : "=r"(u) : "f"(f));
    return u;
}

__device__ __forceinline__ void mma_tf32(float c[4], const uint32_t a[4], const uint32_t b[2]) {
    asm volatile(
        "mma.sync.aligned.m16n8k8.row.col.f32.tf32.tf32.f32 "
        "{%0,%1,%2,%3},{%4,%5,%6,%7},{%8,%9},{%0,%1,%2,%3};"
        : "+f"(c[0]), "+f"(c[1]), "+f"(c[2]), "+f"(c[3])
        : "r"(a[0]), "r"(a[1]), "r"(a[2]), "r"(a[3]), "r"(b[0]), "r"(b[1]));
}

__device__ __forceinline__ void cp16(uint32_t dst, const void* src) {
    asm volatile("cp.async.cg.shared.global [%0], [%1], 16;" :: "r"(dst), "l"(src));
}
__device__ __forceinline__ void cp_commit() {
    asm volatile("cp.async.commit_group;");
}
template <int N> __device__ __forceinline__ void cp_wait() {
    asm volatile("cp.async.wait_group %0;" :: "n"(N));
}

// ---------------------------------------------------------------------------
// Kernel 0: convert x, qkv_w, o_w -> tf32 bit patterns (single grid-stride)
// ---------------------------------------------------------------------------
__global__ void cvt_all_kernel(const float* __restrict__ x,
                               const float* __restrict__ qkv_w,
                               const float* __restrict__ o_w) {
    const int nx = MROWS * EMB / 4;
    const int nq = 3 * EMB * EMB / 4;
    const int no = EMB * EMB / 4;
    const int total = nx + nq + no;
    for (int i = blockIdx.x * blockDim.x + threadIdx.x; i < total;
         i += gridDim.x * blockDim.x) {
        const float4* src;
        uint4* dst;
        if (i < nx)            { src = (const float4*)x + i;          dst = (uint4*)d_xt + i; }
        else if (i < nx + nq)  { src = (const float4*)qkv_w + (i-nx); dst = (uint4*)d_wq + (i-nx); }
        else                   { src = (const float4*)o_w + (i-nx-nq); dst = (uint4*)d_wo + (i-nx-nq); }
        float4 v = *src;
        *dst = make_uint4(f2tf32(v.x), f2tf32(v.y), f2tf32(v.z), f2tf32(v.w));
    }
}

// ---------------------------------------------------------------------------
// Kernel 1: combine bias + mask with column padding to NCP
// ---------------------------------------------------------------------------
__global__ void combine_bias_kernel(const float* __restrict__ table,
                                    const int* __restrict__ rel,
                                    const float* __restrict__ mask) {
    const int h = blockIdx.y;
    const int w = blockIdx.z;
    const int idx = blockIdx.x * blockDim.x + threadIdx.x;
    if (idx >= NNP) return;
    const int i = idx / NCP;
    const int j = idx - i * NCP;
    float v = -1e30f;
    if (j < NTOK)
        v = table[rel[i * NTOK + j] * NHEADS + h] + mask[(size_t)w * NN + i * NTOK + j];
    d_bm[((size_t)(h * NWIN + w)) * NNP + idx] = v;
}

// ---------------------------------------------------------------------------
// tf32 tensor-core GEMM, inputs pre-converted to tf32 in gmem.
// Block 256x64, K-tile 32, double-buffered cp.async, position-paired LDS.64
// fragments (stride 40, conflict-free).
// ---------------------------------------------------------------------------
#define KTILE 32
#define NKIT  6
#define ASTR  40
#define BSTR  40
#define AS_FLOATS (256 * ASTR)   // 10240
#define BS_FLOATS (64 * BSTR)    // 2560
#define GEMM_SMEM_BYTES ((AS_FLOATS + BS_FLOATS) * 2 * 4)  // 102400

__device__ __forceinline__ void g_load_tiles(const float* __restrict__ A,
                                             const float* __restrict__ W,
                                             float* As, float* Bs,
                                             int m0, int n0, int kt, int tid) {
    const int r = tid >> 3;
    const int q = tid & 7;
    uint32_t as_base = (uint32_t)__cvta_generic_to_shared(As);
    uint32_t bs_base = (uint32_t)__cvta_generic_to_shared(Bs);
    #pragma unroll
    for (int it = 0; it < 8; it++) {
        int m = r + it * 32;
        cp16(as_base + (uint32_t)(m * ASTR + q * 4) * 4,
             A + (size_t)(m0 + m) * EMB + kt + q * 4);
    }
    #pragma unroll
    for (int it = 0; it < 2; it++) {
        int n = r + it * 32;
        cp16(bs_base + (uint32_t)(n * BSTR + q * 4) * 4,
             W + (size_t)(n0 + n) * EMB + kt + q * 4);
    }
    cp_commit();
}

__device__ __forceinline__ void g_compute(const float* As, const float* Bs,
                                          float acc[4][4][4], int lane,
                                          int wm, int wn) {
    const int g = lane >> 2;
    const int c2 = (lane & 3) * 2;
    #pragma unroll
    for (int ks = 0; ks < KTILE; ks += 8) {
        const int kb = ks + c2;
        uint32_t af[4][4];
        #pragma unroll
        for (int mt = 0; mt < 4; mt++) {
            const float* ap = As + (wm * 64 + mt * 16 + g) * ASTR + kb;
            float2 lo = *(const float2*)ap;
            float2 hi = *(const float2*)(ap + 8 * ASTR);
            af[mt][0] = __float_as_uint(lo.x);
            af[mt][2] = __float_as_uint(lo.y);
            af[mt][1] = __float_as_uint(hi.x);
            af[mt][3] = __float_as_uint(hi.y);
        }
        uint32_t bf[4][2];
        #pragma unroll
        for (int nt = 0; nt < 4; nt++) {
            const float* bp = Bs + (wn * 32 + nt * 8 + g) * BSTR + kb;
            float2 bb = *(const float2*)bp;
            bf[nt][0] = __float_as_uint(bb.x);
            bf[nt][1] = __float_as_uint(bb.y);
        }
        #pragma unroll
        for (int mt = 0; mt < 4; mt++)
            #pragma unroll
            for (int nt = 0; nt < 4; nt++)
                mma_tf32(acc[mt][nt], af[mt], bf[nt]);
    }
}

// QKV variant: epilogue rounds (acc + bias) to tf32.
// Q,K columns (n0 < 384) -> d_qkv; V columns (n0 >= 384) -> d_vt transposed.
__global__ __launch_bounds__(256, 2) void gemm_qkv_kernel(
    const float* __restrict__ bias) {
    extern __shared__ float sm[];
    float* As[2] = { sm, sm + AS_FLOATS };
    float* Bs[2] = { sm + 2 * AS_FLOATS, sm + 2 * AS_FLOATS + BS_FLOATS };

    const int tid = threadIdx.x;
    const int lane = tid & 31;
    const int wid = tid >> 5;
    const int wm = wid >> 1;
    const int wn = wid & 1;
    const int m0 = blockIdx.y * 256;
    const int n0 = blockIdx.x * 64;

    float acc[4][4][4];
    #pragma unroll
    for (int mt = 0; mt < 4; mt++)
        #pragma unroll
        for (int nt = 0; nt < 4; nt++)
            #pragma unroll
            for (int r = 0; r < 4; r++) acc[mt][nt][r] = 0.f;

    const float* A = d_xt;
    const float* W = d_wq;
    g_load_tiles(A, W, As[0], Bs[0], m0, n0, 0, tid);
    g_load_tiles(A, W, As[1], Bs[1], m0, n0, KTILE, tid);

    #pragma unroll
    for (int it = 0; it < NKIT; it++) {
        if (it < NKIT - 1) cp_wait<1>(); else cp_wait<0>();
        __syncthreads();
        g_compute(As[it & 1], Bs[it & 1], acc, lane, wm, wn);
        __syncthreads();
        if (it + 2 < NKIT)
            g_load_tiles(A, W, As[it & 1], Bs[it & 1], m0, n0, (it + 2) * KTILE, tid);
    }

    const bool is_v = (n0 >= 2 * EMB);   // block-uniform
    #pragma unroll
    for (int mt = 0; mt < 4; mt++) {
        #pragma unroll
        for (int half = 0; half < 2; half++) {
            int mg = m0 + wm * 64 + mt * 16 + (lane >> 2) + half * 8;
            int bb = mg / NTOK;
            int nn = mg - bb * NTOK;
            #pragma unroll
            for (int nt = 0; nt < 4; nt++) {
                int c = n0 + wn * 32 + nt * 8 + (lane & 3) * 2;
                float v0 = __uint_as_float(f2tf32(acc[mt][nt][half * 2 + 0] + bias[c]));
                float v1 = __uint_as_float(f2tf32(acc[mt][nt][half * 2 + 1] + bias[c + 1]));
                if (is_v) {
                    int rem = c - 2 * EMB;
                    int h = rem >> 5;
                    int d = rem & 31;
                    size_t vb = (((size_t)bb * NHEADS + h) * HDIM + d) * VTP + nn;
                    d_vt[vb] = v0;
                    d_vt[vb + VTP] = v1;   // d+1
                } else {
                    int which = c / EMB;
                    int rem = c - which * EMB;
                    int h = rem >> 5;
                    int d = rem & 31;
                    size_t dst = ((((size_t)bb * 3 + which) * NHEADS + h) * NTOK + nn) * HDIM + d;
                    *(float2*)&d_qkv[dst] = make_float2(v0, v1);
                }
            }
        }
    }
}

// Projection variant: fp32 store to final output
__global__ __launch_bounds__(256, 2) void gemm_proj_kernel(
    const float* __restrict__ bias, float* __restrict__ out) {
    extern __shared__ float sm[];
    float* As[2] = { sm, sm + AS_FLOATS };
    float* Bs[2] = { sm + 2 * AS_FLOATS, sm + 2 * AS_FLOATS + BS_FLOATS };

    const int tid = threadIdx.x;
    const int lane = tid & 31;
    const int wid = tid >> 5;
    const int wm = wid >> 1;
    const int wn = wid & 1;
    const int m0 = blockIdx.y * 256;
    const int n0 = blockIdx.x * 64;

    float acc[4][4][4];
    #pragma unroll
    for (int mt = 0; mt < 4; mt++)
        #pragma unroll
        for (int nt = 0; nt < 4; nt++)
            #pragma unroll
            for (int r = 0; r < 4; r++) acc[mt][nt][r] = 0.f;

    const float* A = d_attnout;
    const float* W = d_wo;
    g_load_tiles(A, W, As[0], Bs[0], m0, n0, 0, tid);
    g_load_tiles(A, W, As[1], Bs[1], m0, n0, KTILE, tid);

    #pragma unroll
    for (int it = 0; it < NKIT; it++) {
        if (it < NKIT - 1) cp_wait<1>(); else cp_wait<0>();
        __syncthreads();
        g_compute(As[it & 1], Bs[it & 1], acc, lane, wm, wn);
        __syncthreads();
        if (it + 2 < NKIT)
            g_load_tiles(A, W, As[it & 1], Bs[it & 1], m0, n0, (it + 2) * KTILE, tid);
    }

    #pragma unroll
    for (int mt = 0; mt < 4; mt++) {
        #pragma unroll
        for (int half = 0; half < 2; half++) {
            int mg = m0 + wm * 64 + mt * 16 + (lane >> 2) + half * 8;
            #pragma unroll
            for (int nt = 0; nt < 4; nt++) {
                int c = n0 + wn * 32 + nt * 8 + (lane & 3) * 2;
                float v0 = acc[mt][nt][half * 2 + 0] + bias[c];
                float v1 = acc[mt][nt][half * 2 + 1] + bias[c + 1];
                *(float2*)&out[(size_t)mg * EMB + c] = make_float2(v0, v1);
            }
        }
    }
}

// ---------------------------------------------------------------------------
// Kernel 3: tensor-core attention. One CTA (256 thr, 8 warps) per (b, h),
// each warp owns one m16 Q-row tile. V staged TRANSPOSED ([d][n], smem stride
// 136 ≡ 8 mod 32 -> conflict-free LDS.64 b-frags covering all 112 padded
// tokens). Position-paired fragments throughout.
// ---------------------------------------------------------------------------
#define QSTR 40
#define KSTR 40
#define SQ_FLOATS (128 * QSTR)       // 5120
#define SK_FLOATS (NCP * KSTR)       // 4480
#define SVT_FLOATS (HDIM * SVSTR)    // 4352
#define ATTN_SMEM_BYTES ((SQ_FLOATS + SK_FLOATS + SVT_FLOATS) * 4)  // 55808
#define ATHREADS 256

__global__ __launch_bounds__(ATHREADS, 2) void attn_kernel() {
    extern __shared__ float sh[];
    float* sQ  = sh;
    float* sK  = sQ + SQ_FLOATS;
    float* sVt = sK + SK_FLOATS;

    const int t = threadIdx.x;
    const int lane = t & 31;
    const int w8 = t >> 5;          // warp 0..7, owns Q-rows [w8*16, w8*16+16)

    const int bh = blockIdx.x;
    const int b = bh / NHEADS;
    const int h = bh - b * NHEADS;
    const int win = b & (NWIN - 1);

    const size_t base = (((size_t)b * 3) * NHEADS + h) * (NTOK * HDIM);
    const float* qg = d_qkv + base;
    const float* kg = qg + (size_t)NHEADS * NTOK * HDIM;
    const float* vtg = d_vt + ((size_t)b * NHEADS + h) * (HDIM * VTP);
    const float* bmg = d_bm + (size_t)(h * NWIN + win) * NNP;

    // ---- stage Q/K (row-major) + V^T (28 cp16/row: all 112 token slots) ----
    {
        uint32_t uQ = (uint32_t)__cvta_generic_to_shared(sQ);
        uint32_t uK = (uint32_t)__cvta_generic_to_shared(sK);
        uint32_t uV = (uint32_t)__cvta_generic_to_shared(sVt);
        for (int idx = t; idx < NTOK * 8; idx += ATHREADS) {
            int r = idx >> 3, q = (idx & 7) * 4;
            cp16(uQ + (uint32_t)(r * QSTR + q) * 4, qg + r * HDIM + q);
            cp16(uK + (uint32_t)(r * KSTR + q) * 4, kg + r * HDIM + q);
        }
        for (int idx = t; idx < HDIM * (VTP / 4); idx += ATHREADS) {
            int r = idx / (VTP / 4), q = (idx - r * (VTP / 4)) * 4;
            cp16(uV + (uint32_t)(r * SVSTR + q) * 4, vtg + r * VTP + q);
        }
        cp_commit();
        float4 z = make_float4(0.f, 0.f, 0.f, 0.f);
        for (int idx = t; idx < 30 * 8; idx += ATHREADS) {
            int r = 98 + (idx >> 3), c = (idx & 7) * 4;
            *(float4*)&sQ[r * QSTR + c] = z;
        }
        for (int idx = t; idx < 14 * 8; idx += ATHREADS) {
            int r = 98 + (idx >> 3), c = (idx & 7) * 4;
            *(float4*)&sK[r * KSTR + c] = z;
        }
        cp_wait<0>();
        __syncthreads();
    }

    const int g = lane >> 2;        // quad row
    const int c2 = (lane & 3) * 2;

    // ---- S = Q K^T : c-frags sf[14][4], position-paired LDS.64 frags ----
    float sf[14][4];
    #pragma unroll
    for (int nt = 0; nt < 14; nt++)
        #pragma unroll
        for (int r = 0; r < 4; r++) sf[nt][r] = 0.f;

    #pragma unroll
    for (int ks = 0; ks < 4; ks++) {
        const int kb = ks * 8 + c2;
        const float* ap = sQ + (w8 * 16 + g) * QSTR + kb;
        float2 lo = *(const float2*)ap;
        float2 hi = *(const float2*)(ap + 8 * QSTR);
        uint32_t af[4];
        af[0] = __float_as_uint(lo.x);
        af[2] = __float_as_uint(lo.y);
        af[1] = __float_as_uint(hi.x);
        af[3] = __float_as_uint(hi.y);
        #pragma unroll
        for (int nt = 0; nt < 14; nt++) {
            const float* bp = sK + (nt * 8 + g) * KSTR + kb;
            float2 bb = *(const float2*)bp;
            uint32_t bf[2];
            bf[0] = __float_as_uint(bb.x);
            bf[1] = __float_as_uint(bb.y);
            mma_tf32(sf[nt], af, bf);
        }
    }

    // ---- scale + bias/mask (direct gmem) + row max ----
    const float scale = 0.17677669529663687f;  // 32^-0.5
    float mx[2] = { -1e30f, -1e30f };
    {
        int r0 = w8 * 16 + g;
        int r0c = min(r0, NTOK - 1);
        int r1c = min(r0 + 8, NTOK - 1);
        const float* bm0 = bmg + (size_t)r0c * NCP;
        const float* bm1 = bmg + (size_t)r1c * NCP;
        #pragma unroll
        for (int nt = 0; nt < 14; nt++) {
            int col = nt * 8 + c2;
            float2 b0 = *(const float2*)&bm0[col];
            float2 b1 = *(const float2*)&bm1[col];
            sf[nt][0] = fmaf(sf[nt][0], scale, b0.x);
            sf[nt][1] = fmaf(sf[nt][1], scale, b0.y);
            sf[nt][2] = fmaf(sf[nt][2], scale, b1.x);
            sf[nt][3] = fmaf(sf[nt][3], scale, b1.y);
            mx[0] = fmaxf(mx[0], fmaxf(sf[nt][0], sf[nt][1]));
            mx[1] = fmaxf(mx[1], fmaxf(sf[nt][2], sf[nt][3]));
        }
    }
    #pragma unroll
    for (int hf = 0; hf < 2; hf++) {
        float v = mx[hf];
        v = fmaxf(v, __shfl_xor_sync(0xffffffffu, v, 1));
        v = fmaxf(v, __shfl_xor_sync(0xffffffffu, v, 2));
        mx[hf] = v;
    }

    // ---- exp + row sum ----
    float sum[2] = { 0.f, 0.f };
    #pragma unroll
    for (int nt = 0; nt < 14; nt++) {
        float p0 = __expf(sf[nt][0] - mx[0]);
        float p1 = __expf(sf[nt][1] - mx[0]);
        float p2 = __expf(sf[nt][2] - mx[1]);
        float p3 = __expf(sf[nt][3] - mx[1]);
        sf[nt][0] = p0; sf[nt][1] = p1;
        sf[nt][2] = p2; sf[nt][3] = p3;
        sum[0] += p0 + p1;
        sum[1] += p2 + p3;
    }
    #pragma unroll
    for (int hf = 0; hf < 2; hf++) {
        float v = sum[hf];
        v += __shfl_xor_sync(0xffffffffu, v, 1);
        v += __shfl_xor_sync(0xffffffffu, v, 2);
        sum[hf] = v;
    }

    // ---- O = P V : P c-frag IS the a-frag; V^T b-frag is one LDS.64 ----
    float of[4][4];
    #pragma unroll
    for (int nt = 0; nt < 4; nt++)
        #pragma unroll
        for (int r = 0; r < 4; r++) of[nt][r] = 0.f;

    #pragma unroll
    for (int kt = 0; kt < 14; kt++) {
        uint32_t pa[4];
        pa[0] = f2tf32(sf[kt][0]);   // row g,   token kt*8+2c
        pa[1] = f2tf32(sf[kt][2]);   // row g+8, token kt*8+2c
        pa[2] = f2tf32(sf[kt][1]);   // row g,   token kt*8+2c+1
        pa[3] = f2tf32(sf[kt][3]);   // row g+8, token kt*8+2c+1
        #pragma unroll
        for (int nt = 0; nt < 4; nt++) {
            const float* vp = sVt + (nt * 8 + g) * SVSTR + kt * 8 + c2;
            float2 vv = *(const float2*)vp;
            uint32_t bf[2];
            bf[0] = __float_as_uint(vv.x);   // V[token 2c][d]
            bf[1] = __float_as_uint(vv.y);   // V[token 2c+1][d]
            mma_tf32(of[nt], pa, bf);
        }
    }

    // ---- epilogue: normalize, round to tf32 for proj, store ----
    #pragma unroll
    for (int hf = 0; hf < 2; hf++) {
        int row = w8 * 16 + g + hf * 8;
        if (row < NTOK) {
            float inv = 1.f / sum[hf];
            float* op = d_attnout + ((size_t)b * NTOK + row) * EMB + h * HDIM;
            #pragma unroll
            for (int nt = 0; nt < 4; nt++) {
                int col = nt * 8 + c2;
                float v0 = __uint_as_float(f2tf32(of[nt][hf * 2 + 0] * inv));
                float v1 = __uint_as_float(f2tf32(of[nt][hf * 2 + 1] * inv));
                *(float2*)&op[col] = make_float2(v0, v1);
            }
        }
    }
}

// ---------------------------------------------------------------------------
// Launch
// ---------------------------------------------------------------------------
extern "C" void kernel_launch(void* const* d_in, const int* in_sizes, int n_in,
                              void* d_out, int out_size) {
    const float* x          = (const float*)d_in[0];
    const float* mask       = (const float*)d_in[1];
    const float* qkv_w      = (const float*)d_in[2];
    const float* qkv_b      = (const float*)d_in[3];
    const float* o_w        = (const float*)d_in[4];
    const float* o_b        = (const float*)d_in[5];
    const float* bias_table = (const float*)d_in[6];
    const int*   rel_index  = (const int*)d_in[7];
    float* out = (float*)d_out;

    cudaFuncSetAttribute(gemm_qkv_kernel,
        cudaFuncAttributeMaxDynamicSharedMemorySize, GEMM_SMEM_BYTES);
    cudaFuncSetAttribute(gemm_proj_kernel,
        cudaFuncAttributeMaxDynamicSharedMemorySize, GEMM_SMEM_BYTES);
    cudaFuncSetAttribute(attn_kernel,
        cudaFuncAttributeMaxDynamicSharedMemorySize, ATTN_SMEM_BYTES);

    // pre-conversion + bias/mask combine
    cvt_all_kernel<<<9472, 256>>>(x, qkv_w, o_w);
    combine_bias_kernel<<<dim3((NNP + 255) / 256, NHEADS, NWIN), 256>>>(
        bias_table, rel_index, mask);

    // QKV: M = 200704 (784 tiles of 256), Ncols = 576 (9 tiles of 64)
    gemm_qkv_kernel<<<dim3(9, 784), 256, GEMM_SMEM_BYTES>>>(qkv_b);

    // Attention: one CTA (8 warps) per (b, h)
    attn_kernel<<<BATCH * NHEADS, ATHREADS, ATTN_SMEM_BYTES>>>();

    // Projection: Ncols = 192 (3 tiles of 64)
    gemm_proj_kernel<<<dim3(3, 784), 256, GEMM_SMEM_BYTES>>>(o_b, out);
}

// round 16
// speedup vs baseline: 1.1872x; 1.1872x over previous
#include <cuda_runtime.h>
#include <cuda_fp16.h>
#include <cstddef>
#include <cstdint>

// Problem constants
#define BATCH   2048
#define NTOK    98
#define EMB     192
#define NHEADS  6
#define HDIM    32
#define NWIN    64
#define NN      (NTOK*NTOK)        // 9604
#define NCP     112                // padded key/col dim for attention tiles
#define NNP     (NTOK*NCP)         // 10976 padded bm row block
#define MROWS   (BATCH*NTOK)       // 200704

// Scratch (device globals — no allocation allowed)
__device__ __align__(16) __half d_qkv[(size_t)BATCH * 3 * NHEADS * NTOK * HDIM]; // fp16 Q,K,V [b][which][h][n][d]
__device__ __align__(16) __half d_attnout[(size_t)MROWS * EMB];                  // fp16 [b][n][h*32+d]
__device__ float d_bm[(size_t)NHEADS * NWIN * NNP];                              // bias+mask fp32, padded cols
__device__ __align__(16) __half d_xt[(size_t)MROWS * EMB];                       // fp16 x
__device__ __align__(16) __half d_wq[3 * EMB * EMB];                             // fp16 qkv_w
__device__ __align__(16) __half d_wo[EMB * EMB];                                 // fp16 o_w

// ---------------------------------------------------------------------------
// helpers
// ---------------------------------------------------------------------------
__device__ __forceinline__ void mma_f16(float c[4], const uint32_t a[4], const uint32_t b[2]) {
    asm volatile(
        "mma.sync.aligned.m16n8k16.row.col.f32.f16.f16.f32 "
        "{%0,%1,%2,%3},{%4,%5,%6,%7},{%8,%9},{%0,%1,%2,%3};"
        : "+f"(c[0]), "+f"(c[1]), "+f"(c[2]), "+f"(c[3])
        : "r"(a[0]), "r"(a[1]), "r"(a[2]), "r"(a[3]), "r"(b[0]), "r"(b[1]));
}

__device__ __forceinline__ void cp16(uint32_t dst, const void* src) {
    asm volatile("cp.async.cg.shared.global [%0], [%1], 16;" :: "r"(dst), "l"(src));
}
__device__ __forceinline__ void cp_commit() {
    asm volatile("cp.async.commit_group;");
}
template <int N> __device__ __forceinline__ void cp_wait() {
    asm volatile("cp.async.wait_group %0;" :: "n"(N));
}

__device__ __forceinline__ uint32_t pack_h2(float lo, float hi) {
    __half2 h = __floats2half2_rn(lo, hi);
    return *reinterpret_cast<uint32_t*>(&h);
}

// ---------------------------------------------------------------------------
// Kernel 0: convert x, qkv_w, o_w -> fp16 (single grid-stride, float4 groups)
// ---------------------------------------------------------------------------
__global__ void cvt_all_kernel(const float* __restrict__ x,
                               const float* __restrict__ qkv_w,
                               const float* __restrict__ o_w) {
    const int nx = MROWS * EMB / 4;
    const int nq = 3 * EMB * EMB / 4;
    const int no = EMB * EMB / 4;
    const int total = nx + nq + no;
    for (int i = blockIdx.x * blockDim.x + threadIdx.x; i < total;
         i += gridDim.x * blockDim.x) {
        const float4* src;
        __half* dst;
        if (i < nx)            { src = (const float4*)x + i;           dst = d_xt + (size_t)i * 4; }
        else if (i < nx + nq)  { src = (const float4*)qkv_w + (i-nx);  dst = d_wq + (size_t)(i-nx) * 4; }
        else                   { src = (const float4*)o_w + (i-nx-nq); dst = d_wo + (size_t)(i-nx-nq) * 4; }
        float4 v = *src;
        uint2 u = make_uint2(pack_h2(v.x, v.y), pack_h2(v.z, v.w));
        *(uint2*)dst = u;
    }
}

// ---------------------------------------------------------------------------
// Kernel 1: combine bias + mask with column padding to NCP
// ---------------------------------------------------------------------------
__global__ void combine_bias_kernel(const float* __restrict__ table,
                                    const int* __restrict__ rel,
                                    const float* __restrict__ mask) {
    const int h = blockIdx.y;
    const int w = blockIdx.z;
    const int idx = blockIdx.x * blockDim.x + threadIdx.x;
    if (idx >= NNP) return;
    const int i = idx / NCP;
    const int j = idx - i * NCP;
    float v = -1e30f;
    if (j < NTOK)
        v = table[rel[i * NTOK + j] * NHEADS + h] + mask[(size_t)w * NN + i * NTOK + j];
    d_bm[((size_t)(h * NWIN + w)) * NNP + idx] = v;
}

// ---------------------------------------------------------------------------
// fp16 tensor-core GEMM (m16n8k16), inputs pre-converted to fp16 in gmem.
// Block 256x64, K-tile 32 halves, double-buffered cp.async.
// Position-permuted fragments: slots {2c,2c+1}<-pos{4c,4c+1}, {2c+8,2c+9}<-
// pos{4c+2,4c+3} on BOTH A and B -> each frag pair is one 8B LDS (uint2).
// Smem stride 48 halves: bank g*24+2c distinct per 16-lane phase.
// ---------------------------------------------------------------------------
#define KTILE 32
#define NKIT  6
#define ASTRH 48
#define BSTRH 48
#define AS_HALF (256 * ASTRH)    // 12288
#define BS_HALF (64 * BSTRH)     // 3072
#define GEMM_SMEM_BYTES ((AS_HALF + BS_HALF) * 2 * 2)  // 61440

__device__ __forceinline__ void g_load_tiles(const __half* __restrict__ A,
                                             const __half* __restrict__ W,
                                             __half* As, __half* Bs,
                                             int m0, int n0, int kt, int tid) {
    const int r = tid >> 2;        // 0..63
    const int q = (tid & 3) * 8;   // halves offset (16B chunks)
    uint32_t as_base = (uint32_t)__cvta_generic_to_shared(As);
    uint32_t bs_base = (uint32_t)__cvta_generic_to_shared(Bs);
    #pragma unroll
    for (int it = 0; it < 4; it++) {
        int m = r + it * 64;
        cp16(as_base + (uint32_t)(m * ASTRH + q) * 2,
             A + (size_t)(m0 + m) * EMB + kt + q);
    }
    cp16(bs_base + (uint32_t)(r * BSTRH + q) * 2,
         W + (size_t)(n0 + r) * EMB + kt + q);
    cp_commit();
}

__device__ __forceinline__ void g_compute(const __half* As, const __half* Bs,
                                          float acc[4][4][4], int lane,
                                          int wm, int wn) {
    const int g = lane >> 2;
    const int c4 = (lane & 3) * 4;
    #pragma unroll
    for (int ks = 0; ks < 2; ks++) {          // two k16 steps cover KTILE=32
        const int kb = ks * 16 + c4;
        uint32_t af[4][4];
        #pragma unroll
        for (int mt = 0; mt < 4; mt++) {
            const __half* ap = As + (wm * 64 + mt * 16 + g) * ASTRH + kb;
            uint2 lo = *(const uint2*)ap;                  // row g:   pos 4c..4c+3
            uint2 hi = *(const uint2*)(ap + 8 * ASTRH);    // row g+8
            af[mt][0] = lo.x;   // a0: k slots 2c,2c+1
            af[mt][1] = hi.x;   // a1
            af[mt][2] = lo.y;   // a2: k slots 2c+8,2c+9
            af[mt][3] = hi.y;   // a3
        }
        uint32_t bf[4][2];
        #pragma unroll
        for (int nt = 0; nt < 4; nt++) {
            const __half* bp = Bs + (wn * 32 + nt * 8 + g) * BSTRH + kb;
            uint2 bb = *(const uint2*)bp;
            bf[nt][0] = bb.x;
            bf[nt][1] = bb.y;
        }
        #pragma unroll
        for (int mt = 0; mt < 4; mt++)
            #pragma unroll
            for (int nt = 0; nt < 4; nt++)
                mma_f16(acc[mt][nt], af[mt], bf[nt]);
    }
}

// QKV variant: epilogue (acc + bias) -> fp16 half2, permuted into d_qkv
__global__ __launch_bounds__(256, 2) void gemm_qkv_kernel(
    const float* __restrict__ bias) {
    extern __shared__ __half smh[];
    __half* As[2] = { smh, smh + AS_HALF };
    __half* Bs[2] = { smh + 2 * AS_HALF, smh + 2 * AS_HALF + BS_HALF };

    const int tid = threadIdx.x;
    const int lane = tid & 31;
    const int wid = tid >> 5;
    const int wm = wid >> 1;
    const int wn = wid & 1;
    const int m0 = blockIdx.y * 256;
    const int n0 = blockIdx.x * 64;

    float acc[4][4][4];
    #pragma unroll
    for (int mt = 0; mt < 4; mt++)
        #pragma unroll
        for (int nt = 0; nt < 4; nt++)
            #pragma unroll
            for (int r = 0; r < 4; r++) acc[mt][nt][r] = 0.f;

    const __half* A = d_xt;
    const __half* W = d_wq;
    g_load_tiles(A, W, As[0], Bs[0], m0, n0, 0, tid);
    g_load_tiles(A, W, As[1], Bs[1], m0, n0, KTILE, tid);

    #pragma unroll
    for (int it = 0; it < NKIT; it++) {
        if (it < NKIT - 1) cp_wait<1>(); else cp_wait<0>();
        __syncthreads();
        g_compute(As[it & 1], Bs[it & 1], acc, lane, wm, wn);
        __syncthreads();
        if (it + 2 < NKIT)
            g_load_tiles(A, W, As[it & 1], Bs[it & 1], m0, n0, (it + 2) * KTILE, tid);
    }

    #pragma unroll
    for (int mt = 0; mt < 4; mt++) {
        #pragma unroll
        for (int half = 0; half < 2; half++) {
            int mg = m0 + wm * 64 + mt * 16 + (lane >> 2) + half * 8;
            int bb = mg / NTOK;
            int nn = mg - bb * NTOK;
            #pragma unroll
            for (int nt = 0; nt < 4; nt++) {
                int c = n0 + wn * 32 + nt * 8 + (lane & 3) * 2;
                int which = c / EMB;
                int rem = c - which * EMB;
                int h = rem >> 5;
                int d = rem & 31;
                size_t dst = ((((size_t)bb * 3 + which) * NHEADS + h) * NTOK + nn) * HDIM + d;
                uint32_t hv = pack_h2(acc[mt][nt][half * 2 + 0] + bias[c],
                                      acc[mt][nt][half * 2 + 1] + bias[c + 1]);
                *(uint32_t*)&d_qkv[dst] = hv;
            }
        }
    }
}

// Projection variant: fp32 store to final output
__global__ __launch_bounds__(256, 2) void gemm_proj_kernel(
    const float* __restrict__ bias, float* __restrict__ out) {
    extern __shared__ __half smh[];
    __half* As[2] = { smh, smh + AS_HALF };
    __half* Bs[2] = { smh + 2 * AS_HALF, smh + 2 * AS_HALF + BS_HALF };

    const int tid = threadIdx.x;
    const int lane = tid & 31;
    const int wid = tid >> 5;
    const int wm = wid >> 1;
    const int wn = wid & 1;
    const int m0 = blockIdx.y * 256;
    const int n0 = blockIdx.x * 64;

    float acc[4][4][4];
    #pragma unroll
    for (int mt = 0; mt < 4; mt++)
        #pragma unroll
        for (int nt = 0; nt < 4; nt++)
            #pragma unroll
            for (int r = 0; r < 4; r++) acc[mt][nt][r] = 0.f;

    const __half* A = d_attnout;
    const __half* W = d_wo;
    g_load_tiles(A, W, As[0], Bs[0], m0, n0, 0, tid);
    g_load_tiles(A, W, As[1], Bs[1], m0, n0, KTILE, tid);

    #pragma unroll
    for (int it = 0; it < NKIT; it++) {
        if (it < NKIT - 1) cp_wait<1>(); else cp_wait<0>();
        __syncthreads();
        g_compute(As[it & 1], Bs[it & 1], acc, lane, wm, wn);
        __syncthreads();
        if (it + 2 < NKIT)
            g_load_tiles(A, W, As[it & 1], Bs[it & 1], m0, n0, (it + 2) * KTILE, tid);
    }

    #pragma unroll
    for (int mt = 0; mt < 4; mt++) {
        #pragma unroll
        for (int half = 0; half < 2; half++) {
            int mg = m0 + wm * 64 + mt * 16 + (lane >> 2) + half * 8;
            #pragma unroll
            for (int nt = 0; nt < 4; nt++) {
                int c = n0 + wn * 32 + nt * 8 + (lane & 3) * 2;
                float v0 = acc[mt][nt][half * 2 + 0] + bias[c];
                float v1 = acc[mt][nt][half * 2 + 1] + bias[c + 1];
                *(float2*)&out[(size_t)mg * EMB + c] = make_float2(v0, v1);
            }
        }
    }
}

// ---------------------------------------------------------------------------
// Kernel 3: fp16 tensor-core attention. One CTA (256 thr, 8 warps) per (b,h),
// each warp owns one m16 Q-row tile.
//  - QK^T: m16n8k16, position-permuted uint2 frags (stride 48 halves).
//  - softmax fp32 in c-frags (unchanged).
//  - PV: identity token mapping — P c-frag tile-pair IS the a-frag (pure
//    half2 packs, zero LDS/shfl); V transposed in smem ([d][token], stride
//    120 halves: bank g*28+c distinct) -> b-frags are single LDS.32.
// ---------------------------------------------------------------------------
#define QSTRH 48
#define KSTRH 48
#define VSTRH 120
#define SQ_HALF (128 * QSTRH)        // 6144
#define SK_HALF (NCP * KSTRH)        // 5376
#define SVT_HALF (HDIM * VSTRH)      // 3840
#define ATTN_SMEM_BYTES ((SQ_HALF + SK_HALF + SVT_HALF) * 2)  // 30720
#define ATHREADS 256

__global__ __launch_bounds__(ATHREADS, 2) void attn_kernel() {
    extern __shared__ __half shh[];
    __half* sQ  = shh;
    __half* sK  = sQ + SQ_HALF;
    __half* sVt = sK + SK_HALF;

    const int t = threadIdx.x;
    const int lane = t & 31;
    const int w8 = t >> 5;          // warp 0..7, owns Q-rows [w8*16, w8*16+16)

    const int bh = blockIdx.x;
    const int b = bh / NHEADS;
    const int h = bh - b * NHEADS;
    const int win = b & (NWIN - 1);

    const size_t base = (((size_t)b * 3) * NHEADS + h) * (NTOK * HDIM);
    const __half* qg = d_qkv + base;
    const __half* kg = qg + (size_t)NHEADS * NTOK * HDIM;
    const __half* vg = qg + 2 * (size_t)NHEADS * NTOK * HDIM;
    const float* bmg = d_bm + (size_t)(h * NWIN + win) * NNP;

    // ---- stage Q/K via cp.async; V via coalesced LDG -> transposed STS ----
    {
        uint32_t uQ = (uint32_t)__cvta_generic_to_shared(sQ);
        uint32_t uK = (uint32_t)__cvta_generic_to_shared(sK);
        for (int idx = t; idx < NTOK * 4; idx += ATHREADS) {
            int r = idx >> 2, q = (idx & 3) * 8;
            cp16(uQ + (uint32_t)(r * QSTRH + q) * 2, qg + r * HDIM + q);
            cp16(uK + (uint32_t)(r * KSTRH + q) * 2, kg + r * HDIM + q);
        }
        cp_commit();
        // zero pad rows (uint2 = 4 halves, 8 per 32-half row)
        for (int idx = t; idx < 30 * 8; idx += ATHREADS) {
            int r = 98 + (idx >> 3), c = (idx & 7) * 4;
            *(uint2*)&sQ[r * QSTRH + c] = make_uint2(0u, 0u);
        }
        for (int idx = t; idx < 14 * 8; idx += ATHREADS) {
            int r = 98 + (idx >> 3), c = (idx & 7) * 4;
            *(uint2*)&sK[r * KSTRH + c] = make_uint2(0u, 0u);
        }
        // V transpose: i -> token tkn = i/16, d-pair d2 = i%16 (coalesced LDG)
        for (int i = t; i < NCP * 16; i += ATHREADS) {
            int tkn = i >> 4, d2 = i & 15;
            __half2 v2 = (tkn < NTOK)
                ? *(const __half2*)&vg[tkn * HDIM + d2 * 2]
                : __half2(__float2half_rn(0.f), __float2half_rn(0.f));
            sVt[(2 * d2 + 0) * VSTRH + tkn] = __low2half(v2);
            sVt[(2 * d2 + 1) * VSTRH + tkn] = __high2half(v2);
        }
        cp_wait<0>();
        __syncthreads();
    }

    const int g = lane >> 2;        // quad row
    const int c = lane & 3;         // quad pos
    const int c2 = c * 2;
    const int c4 = c * 4;

    // ---- S = Q K^T : c-frags sf[14][4]; 2 k16 steps over HDIM=32 ----
    float sf[14][4];
    #pragma unroll
    for (int nt = 0; nt < 14; nt++)
        #pragma unroll
        for (int r = 0; r < 4; r++) sf[nt][r] = 0.f;

    #pragma unroll
    for (int ks = 0; ks < 2; ks++) {
        const int kb = ks * 16 + c4;
        const __half* ap = sQ + (w8 * 16 + g) * QSTRH + kb;
        uint2 lo = *(const uint2*)ap;
        uint2 hi = *(const uint2*)(ap + 8 * QSTRH);
        uint32_t af[4];
        af[0] = lo.x;
        af[1] = hi.x;
        af[2] = lo.y;
        af[3] = hi.y;
        #pragma unroll
        for (int nt = 0; nt < 14; nt++) {
            const __half* bp = sK + (nt * 8 + g) * KSTRH + kb;
            uint2 bb = *(const uint2*)bp;
            uint32_t bf[2] = { bb.x, bb.y };
            mma_f16(sf[nt], af, bf);
        }
    }

    // ---- scale + bias/mask (direct gmem, L2-resident) + row max ----
    const float scale = 0.17677669529663687f;  // 32^-0.5
    float mx[2] = { -1e30f, -1e30f };
    {
        int r0 = w8 * 16 + g;
        int r0c = min(r0, NTOK - 1);
        int r1c = min(r0 + 8, NTOK - 1);
        const float* bm0 = bmg + (size_t)r0c * NCP;
        const float* bm1 = bmg + (size_t)r1c * NCP;
        #pragma unroll
        for (int nt = 0; nt < 14; nt++) {
            int col = nt * 8 + c2;
            float2 b0 = *(const float2*)&bm0[col];
            float2 b1 = *(const float2*)&bm1[col];
            sf[nt][0] = fmaf(sf[nt][0], scale, b0.x);
            sf[nt][1] = fmaf(sf[nt][1], scale, b0.y);
            sf[nt][2] = fmaf(sf[nt][2], scale, b1.x);
            sf[nt][3] = fmaf(sf[nt][3], scale, b1.y);
            mx[0] = fmaxf(mx[0], fmaxf(sf[nt][0], sf[nt][1]));
            mx[1] = fmaxf(mx[1], fmaxf(sf[nt][2], sf[nt][3]));
        }
    }
    #pragma unroll
    for (int hf = 0; hf < 2; hf++) {
        float v = mx[hf];
        v = fmaxf(v, __shfl_xor_sync(0xffffffffu, v, 1));
        v = fmaxf(v, __shfl_xor_sync(0xffffffffu, v, 2));
        mx[hf] = v;
    }

    // ---- exp + row sum ----
    float sum[2] = { 0.f, 0.f };
    #pragma unroll
    for (int nt = 0; nt < 14; nt++) {
        float p0 = __expf(sf[nt][0] - mx[0]);
        float p1 = __expf(sf[nt][1] - mx[0]);
        float p2 = __expf(sf[nt][2] - mx[1]);
        float p3 = __expf(sf[nt][3] - mx[1]);
        sf[nt][0] = p0; sf[nt][1] = p1;
        sf[nt][2] = p2; sf[nt][3] = p3;
        sum[0] += p0 + p1;
        sum[1] += p2 + p3;
    }
    #pragma unroll
    for (int hf = 0; hf < 2; hf++) {
        float v = sum[hf];
        v += __shfl_xor_sync(0xffffffffu, v, 1);
        v += __shfl_xor_sync(0xffffffffu, v, 2);
        sum[hf] = v;
    }

    // ---- O = P V : identity token mapping; a-frag = half2 packs of the
    //      c-frag tile pair; b-frag = one LDS.32 from sVt ----
    float of[4][4];
    #pragma unroll
    for (int nt = 0; nt < 4; nt++)
        #pragma unroll
        for (int r = 0; r < 4; r++) of[nt][r] = 0.f;

    #pragma unroll
    for (int kt = 0; kt < 7; kt++) {          // 7 k16 steps over 112 tokens
        uint32_t pa[4];
        pa[0] = pack_h2(sf[2*kt][0],   sf[2*kt][1]);    // row g,   tokens 16kt+2c,+2c+1
        pa[1] = pack_h2(sf[2*kt][2],   sf[2*kt][3]);    // row g+8
        pa[2] = pack_h2(sf[2*kt+1][0], sf[2*kt+1][1]);  // row g,   tokens 16kt+8+2c,..
        pa[3] = pack_h2(sf[2*kt+1][2], sf[2*kt+1][3]);  // row g+8
        #pragma unroll
        for (int nt = 0; nt < 4; nt++) {
            const __half* vp = sVt + (nt * 8 + g) * VSTRH + kt * 16;
            uint32_t bf[2];
            bf[0] = *(const uint32_t*)(vp + c2);        // tokens 16kt+2c,+2c+1
            bf[1] = *(const uint32_t*)(vp + 8 + c2);    // tokens 16kt+8+2c,..
            mma_f16(of[nt], pa, bf);
        }
    }

    // ---- epilogue: normalize, store fp16 for proj ----
    #pragma unroll
    for (int hf = 0; hf < 2; hf++) {
        int row = w8 * 16 + g + hf * 8;
        if (row < NTOK) {
            float inv = 1.f / sum[hf];
            __half* op = d_attnout + ((size_t)b * NTOK + row) * EMB + h * HDIM;
            #pragma unroll
            for (int nt = 0; nt < 4; nt++) {
                int col = nt * 8 + c2;
                uint32_t hv = pack_h2(of[nt][hf * 2 + 0] * inv,
                                      of[nt][hf * 2 + 1] * inv);
                *(uint32_t*)&op[col] = hv;
            }
        }
    }
}

// ---------------------------------------------------------------------------
// Launch
// ---------------------------------------------------------------------------
extern "C" void kernel_launch(void* const* d_in, const int* in_sizes, int n_in,
                              void* d_out, int out_size) {
    const float* x          = (const float*)d_in[0];
    const float* mask       = (const float*)d_in[1];
    const float* qkv_w      = (const float*)d_in[2];
    const float* qkv_b      = (const float*)d_in[3];
    const float* o_w        = (const float*)d_in[4];
    const float* o_b        = (const float*)d_in[5];
    const float* bias_table = (const float*)d_in[6];
    const int*   rel_index  = (const int*)d_in[7];
    float* out = (float*)d_out;

    cudaFuncSetAttribute(gemm_qkv_kernel,
        cudaFuncAttributeMaxDynamicSharedMemorySize, GEMM_SMEM_BYTES);
    cudaFuncSetAttribute(gemm_proj_kernel,
        cudaFuncAttributeMaxDynamicSharedMemorySize, GEMM_SMEM_BYTES);
    cudaFuncSetAttribute(attn_kernel,
        cudaFuncAttributeMaxDynamicSharedMemorySize, ATTN_SMEM_BYTES);

    // pre-conversion + bias/mask combine
    cvt_all_kernel<<<9472, 256>>>(x, qkv_w, o_w);
    combine_bias_kernel<<<dim3((NNP + 255) / 256, NHEADS, NWIN), 256>>>(
        bias_table, rel_index, mask);

    // QKV: M = 200704 (784 tiles of 256), Ncols = 576 (9 tiles of 64)
    gemm_qkv_kernel<<<dim3(9, 784), 256, GEMM_SMEM_BYTES>>>(qkv_b);

    // Attention: one CTA (8 warps) per (b, h)
    attn_kernel<<<BATCH * NHEADS, ATHREADS, ATTN_SMEM_BYTES>>>();

    // Projection: Ncols = 192 (3 tiles of 64)
    gemm_proj_kernel<<<dim3(3, 784), 256, GEMM_SMEM_BYTES>>>(o_b, out);
}

// round 17
// speedup vs baseline: 1.3944x; 1.1746x over previous
#include <cuda_runtime.h>
#include <cuda_fp16.h>
#include <cstddef>
#include <cstdint>

// Problem constants
#define BATCH   2048
#define NTOK    98
#define EMB     192
#define NHEADS  6
#define HDIM    32
#define NWIN    64
#define NN      (NTOK*NTOK)        // 9604
#define NCP     112                // padded key/col dim for attention tiles
#define NNP     (NTOK*NCP)         // 10976 padded bm row block
#define MROWS   (BATCH*NTOK)       // 200704

// Scratch (device globals — no allocation allowed)
__device__ __align__(16) __half d_qkv[(size_t)BATCH * 3 * NHEADS * NTOK * HDIM]; // fp16 Q,K,V [b][which][h][n][d]
__device__ __align__(16) __half d_attnout[(size_t)MROWS * EMB];                  // fp16 [b][n][h*32+d]
__device__ float d_bm[(size_t)NHEADS * NWIN * NNP];                              // bias+mask fp32, padded cols
__device__ __align__(16) __half d_xt[(size_t)MROWS * EMB];                       // fp16 x
__device__ __align__(16) __half d_wq[3 * EMB * EMB];                             // fp16 qkv_w
__device__ __align__(16) __half d_wo[EMB * EMB];                                 // fp16 o_w

// ---------------------------------------------------------------------------
// helpers
// ---------------------------------------------------------------------------
__device__ __forceinline__ void mma_f16(float c[4], const uint32_t a[4], const uint32_t b[2]) {
    asm volatile(
        "mma.sync.aligned.m16n8k16.row.col.f32.f16.f16.f32 "
        "{%0,%1,%2,%3},{%4,%5,%6,%7},{%8,%9},{%0,%1,%2,%3};"
        : "+f"(c[0]), "+f"(c[1]), "+f"(c[2]), "+f"(c[3])
        : "r"(a[0]), "r"(a[1]), "r"(a[2]), "r"(a[3]), "r"(b[0]), "r"(b[1]));
}

__device__ __forceinline__ void ldsm_x2_trans(uint32_t& r0, uint32_t& r1, uint32_t addr) {
    asm volatile("ldmatrix.sync.aligned.m8n8.x2.trans.shared.b16 {%0,%1}, [%2];"
        : "=r"(r0), "=r"(r1) : "r"(addr));
}

__device__ __forceinline__ void cp16(uint32_t dst, const void* src) {
    asm volatile("cp.async.cg.shared.global [%0], [%1], 16;" :: "r"(dst), "l"(src));
}
__device__ __forceinline__ void cp_commit() {
    asm volatile("cp.async.commit_group;");
}
template <int N> __device__ __forceinline__ void cp_wait() {
    asm volatile("cp.async.wait_group %0;" :: "n"(N));
}

__device__ __forceinline__ uint32_t pack_h2(float lo, float hi) {
    __half2 h = __floats2half2_rn(lo, hi);
    return *reinterpret_cast<uint32_t*>(&h);
}

// ---------------------------------------------------------------------------
// Kernel 0: convert x, qkv_w, o_w -> fp16 (single grid-stride, float4 groups)
// ---------------------------------------------------------------------------
__global__ void cvt_all_kernel(const float* __restrict__ x,
                               const float* __restrict__ qkv_w,
                               const float* __restrict__ o_w) {
    const int nx = MROWS * EMB / 4;
    const int nq = 3 * EMB * EMB / 4;
    const int no = EMB * EMB / 4;
    const int total = nx + nq + no;
    for (int i = blockIdx.x * blockDim.x + threadIdx.x; i < total;
         i += gridDim.x * blockDim.x) {
        const float4* src;
        __half* dst;
        if (i < nx)            { src = (const float4*)x + i;           dst = d_xt + (size_t)i * 4; }
        else if (i < nx + nq)  { src = (const float4*)qkv_w + (i-nx);  dst = d_wq + (size_t)(i-nx) * 4; }
        else                   { src = (const float4*)o_w + (i-nx-nq); dst = d_wo + (size_t)(i-nx-nq) * 4; }
        float4 v = *src;
        uint2 u = make_uint2(pack_h2(v.x, v.y), pack_h2(v.z, v.w));
        *(uint2*)dst = u;
    }
}

// ---------------------------------------------------------------------------
// Kernel 1: combine bias + mask with column padding to NCP
// ---------------------------------------------------------------------------
__global__ void combine_bias_kernel(const float* __restrict__ table,
                                    const int* __restrict__ rel,
                                    const float* __restrict__ mask) {
    const int h = blockIdx.y;
    const int w = blockIdx.z;
    const int idx = blockIdx.x * blockDim.x + threadIdx.x;
    if (idx >= NNP) return;
    const int i = idx / NCP;
    const int j = idx - i * NCP;
    float v = -1e30f;
    if (j < NTOK)
        v = table[rel[i * NTOK + j] * NHEADS + h] + mask[(size_t)w * NN + i * NTOK + j];
    d_bm[((size_t)(h * NWIN + w)) * NNP + idx] = v;
}

// ---------------------------------------------------------------------------
// fp16 tensor-core GEMM (m16n8k16) — unchanged from round 16.
// ---------------------------------------------------------------------------
#define KTILE 32
#define NKIT  6
#define ASTRH 48
#define BSTRH 48
#define AS_HALF (256 * ASTRH)    // 12288
#define BS_HALF (64 * BSTRH)     // 3072
#define GEMM_SMEM_BYTES ((AS_HALF + BS_HALF) * 2 * 2)  // 61440

__device__ __forceinline__ void g_load_tiles(const __half* __restrict__ A,
                                             const __half* __restrict__ W,
                                             __half* As, __half* Bs,
                                             int m0, int n0, int kt, int tid) {
    const int r = tid >> 2;        // 0..63
    const int q = (tid & 3) * 8;   // halves offset (16B chunks)
    uint32_t as_base = (uint32_t)__cvta_generic_to_shared(As);
    uint32_t bs_base = (uint32_t)__cvta_generic_to_shared(Bs);
    #pragma unroll
    for (int it = 0; it < 4; it++) {
        int m = r + it * 64;
        cp16(as_base + (uint32_t)(m * ASTRH + q) * 2,
             A + (size_t)(m0 + m) * EMB + kt + q);
    }
    cp16(bs_base + (uint32_t)(r * BSTRH + q) * 2,
         W + (size_t)(n0 + r) * EMB + kt + q);
    cp_commit();
}

__device__ __forceinline__ void g_compute(const __half* As, const __half* Bs,
                                          float acc[4][4][4], int lane,
                                          int wm, int wn) {
    const int g = lane >> 2;
    const int c4 = (lane & 3) * 4;
    #pragma unroll
    for (int ks = 0; ks < 2; ks++) {          // two k16 steps cover KTILE=32
        const int kb = ks * 16 + c4;
        uint32_t af[4][4];
        #pragma unroll
        for (int mt = 0; mt < 4; mt++) {
            const __half* ap = As + (wm * 64 + mt * 16 + g) * ASTRH + kb;
            uint2 lo = *(const uint2*)ap;
            uint2 hi = *(const uint2*)(ap + 8 * ASTRH);
            af[mt][0] = lo.x;
            af[mt][1] = hi.x;
            af[mt][2] = lo.y;
            af[mt][3] = hi.y;
        }
        uint32_t bf[4][2];
        #pragma unroll
        for (int nt = 0; nt < 4; nt++) {
            const __half* bp = Bs + (wn * 32 + nt * 8 + g) * BSTRH + kb;
            uint2 bb = *(const uint2*)bp;
            bf[nt][0] = bb.x;
            bf[nt][1] = bb.y;
        }
        #pragma unroll
        for (int mt = 0; mt < 4; mt++)
            #pragma unroll
            for (int nt = 0; nt < 4; nt++)
                mma_f16(acc[mt][nt], af[mt], bf[nt]);
    }
}

// QKV variant: epilogue (acc + bias) -> fp16 half2, permuted into d_qkv
__global__ __launch_bounds__(256, 2) void gemm_qkv_kernel(
    const float* __restrict__ bias) {
    extern __shared__ __half smh[];
    __half* As[2] = { smh, smh + AS_HALF };
    __half* Bs[2] = { smh + 2 * AS_HALF, smh + 2 * AS_HALF + BS_HALF };

    const int tid = threadIdx.x;
    const int lane = tid & 31;
    const int wid = tid >> 5;
    const int wm = wid >> 1;
    const int wn = wid & 1;
    const int m0 = blockIdx.y * 256;
    const int n0 = blockIdx.x * 64;

    float acc[4][4][4];
    #pragma unroll
    for (int mt = 0; mt < 4; mt++)
        #pragma unroll
        for (int nt = 0; nt < 4; nt++)
            #pragma unroll
            for (int r = 0; r < 4; r++) acc[mt][nt][r] = 0.f;

    const __half* A = d_xt;
    const __half* W = d_wq;
    g_load_tiles(A, W, As[0], Bs[0], m0, n0, 0, tid);
    g_load_tiles(A, W, As[1], Bs[1], m0, n0, KTILE, tid);

    #pragma unroll
    for (int it = 0; it < NKIT; it++) {
        if (it < NKIT - 1) cp_wait<1>(); else cp_wait<0>();
        __syncthreads();
        g_compute(As[it & 1], Bs[it & 1], acc, lane, wm, wn);
        __syncthreads();
        if (it + 2 < NKIT)
            g_load_tiles(A, W, As[it & 1], Bs[it & 1], m0, n0, (it + 2) * KTILE, tid);
    }

    #pragma unroll
    for (int mt = 0; mt < 4; mt++) {
        #pragma unroll
        for (int half = 0; half < 2; half++) {
            int mg = m0 + wm * 64 + mt * 16 + (lane >> 2) + half * 8;
            int bb = mg / NTOK;
            int nn = mg - bb * NTOK;
            #pragma unroll
            for (int nt = 0; nt < 4; nt++) {
                int c = n0 + wn * 32 + nt * 8 + (lane & 3) * 2;
                int which = c / EMB;
                int rem = c - which * EMB;
                int h = rem >> 5;
                int d = rem & 31;
                size_t dst = ((((size_t)bb * 3 + which) * NHEADS + h) * NTOK + nn) * HDIM + d;
                uint32_t hv = pack_h2(acc[mt][nt][half * 2 + 0] + bias[c],
                                      acc[mt][nt][half * 2 + 1] + bias[c + 1]);
                *(uint32_t*)&d_qkv[dst] = hv;
            }
        }
    }
}

// Projection variant: fp32 store to final output
__global__ __launch_bounds__(256, 2) void gemm_proj_kernel(
    const float* __restrict__ bias, float* __restrict__ out) {
    extern __shared__ __half smh[];
    __half* As[2] = { smh, smh + AS_HALF };
    __half* Bs[2] = { smh + 2 * AS_HALF, smh + 2 * AS_HALF + BS_HALF };

    const int tid = threadIdx.x;
    const int lane = tid & 31;
    const int wid = tid >> 5;
    const int wm = wid >> 1;
    const int wn = wid & 1;
    const int m0 = blockIdx.y * 256;
    const int n0 = blockIdx.x * 64;

    float acc[4][4][4];
    #pragma unroll
    for (int mt = 0; mt < 4; mt++)
        #pragma unroll
        for (int nt = 0; nt < 4; nt++)
            #pragma unroll
            for (int r = 0; r < 4; r++) acc[mt][nt][r] = 0.f;

    const __half* A = d_attnout;
    const __half* W = d_wo;
    g_load_tiles(A, W, As[0], Bs[0], m0, n0, 0, tid);
    g_load_tiles(A, W, As[1], Bs[1], m0, n0, KTILE, tid);

    #pragma unroll
    for (int it = 0; it < NKIT; it++) {
        if (it < NKIT - 1) cp_wait<1>(); else cp_wait<0>();
        __syncthreads();
        g_compute(As[it & 1], Bs[it & 1], acc, lane, wm, wn);
        __syncthreads();
        if (it + 2 < NKIT)
            g_load_tiles(A, W, As[it & 1], Bs[it & 1], m0, n0, (it + 2) * KTILE, tid);
    }

    #pragma unroll
    for (int mt = 0; mt < 4; mt++) {
        #pragma unroll
        for (int half = 0; half < 2; half++) {
            int mg = m0 + wm * 64 + mt * 16 + (lane >> 2) + half * 8;
            #pragma unroll
            for (int nt = 0; nt < 4; nt++) {
                int c = n0 + wn * 32 + nt * 8 + (lane & 3) * 2;
                float v0 = acc[mt][nt][half * 2 + 0] + bias[c];
                float v1 = acc[mt][nt][half * 2 + 1] + bias[c + 1];
                *(float2*)&out[(size_t)mg * EMB + c] = make_float2(v0, v1);
            }
        }
    }
}

// ---------------------------------------------------------------------------
// Kernel 3: fp16 tensor-core attention. One CTA (256 thr, 8 warps) per (b,h).
//  - Q/K/V all staged row-major via cp.async (group 0).
//  - bias+mask tile prefetched to smem via cp.async (group 1), waited AFTER
//    the QK mma phase -> its gmem latency fully hidden.
//  - QK^T: m16n8k16, position-permuted uint2 frags.
//  - PV: P c-frag tile-pair IS the a-frag (half2 packs); V b-frags via
//    ldmatrix.x2.trans on row-major V (hardware transpose, conflict-free).
// ---------------------------------------------------------------------------
#define QSTRH 48
#define KSTRH 48
#define VSTRH 40
#define BMSTR 116                    // smem floats per bm row (16B-aligned rows)
#define SQ_HALF (128 * QSTRH)        // 6144
#define SK_HALF (NCP * KSTRH)        // 5376
#define SV_HALF (NCP * VSTRH)        // 4480
#define SBM_FLOATS (NTOK * BMSTR)    // 11368
#define ATTN_SMEM_BYTES ((SQ_HALF + SK_HALF + SV_HALF) * 2 + SBM_FLOATS * 4)  // 77472
#define ATHREADS 256

__global__ __launch_bounds__(ATHREADS, 2) void attn_kernel() {
    extern __shared__ __half shh[];
    __half* sQ  = shh;
    __half* sK  = sQ + SQ_HALF;
    __half* sV  = sK + SK_HALF;
    float*  sBM = (float*)(sV + SV_HALF);

    const int t = threadIdx.x;
    const int lane = t & 31;
    const int w8 = t >> 5;          // warp 0..7, owns Q-rows [w8*16, w8*16+16)

    const int bh = blockIdx.x;
    const int b = bh / NHEADS;
    const int h = bh - b * NHEADS;
    const int win = b & (NWIN - 1);

    const size_t base = (((size_t)b * 3) * NHEADS + h) * (NTOK * HDIM);
    const __half* qg = d_qkv + base;
    const __half* kg = qg + (size_t)NHEADS * NTOK * HDIM;
    const __half* vg = qg + 2 * (size_t)NHEADS * NTOK * HDIM;
    const float* bmg = d_bm + (size_t)(h * NWIN + win) * NNP;

    // ---- stage: group 0 = Q/K/V rows, group 1 = bias+mask tile ----
    const uint32_t uQ = (uint32_t)__cvta_generic_to_shared(sQ);
    const uint32_t uK = (uint32_t)__cvta_generic_to_shared(sK);
    const uint32_t uV = (uint32_t)__cvta_generic_to_shared(sV);
    const uint32_t uB = (uint32_t)__cvta_generic_to_shared(sBM);
    {
        for (int idx = t; idx < NTOK * 4; idx += ATHREADS) {
            int r = idx >> 2, q = (idx & 3) * 8;
            cp16(uQ + (uint32_t)(r * QSTRH + q) * 2, qg + r * HDIM + q);
            cp16(uK + (uint32_t)(r * KSTRH + q) * 2, kg + r * HDIM + q);
            cp16(uV + (uint32_t)(r * VSTRH + q) * 2, vg + r * HDIM + q);
        }
        cp_commit();                                   // group 0: QKV
        for (int idx = t; idx < NTOK * 28; idx += ATHREADS) {
            int r = idx / 28, q = (idx - r * 28) * 4;
            cp16(uB + (uint32_t)(r * BMSTR + q) * 4, bmg + r * NCP + q);
        }
        cp_commit();                                   // group 1: BM
        // zero pad rows (values never matter; keeps memory defined)
        for (int idx = t; idx < 30 * 8; idx += ATHREADS) {
            int r = 98 + (idx >> 3), c = (idx & 7) * 4;
            *(uint2*)&sQ[r * QSTRH + c] = make_uint2(0u, 0u);
        }
        for (int idx = t; idx < 14 * 8; idx += ATHREADS) {
            int r = 98 + (idx >> 3), c = (idx & 7) * 4;
            *(uint2*)&sK[r * KSTRH + c] = make_uint2(0u, 0u);
            *(uint2*)&sV[r * VSTRH + c] = make_uint2(0u, 0u);
        }
        cp_wait<1>();                                  // QKV landed (BM may fly)
        __syncthreads();
    }

    const int g = lane >> 2;        // quad row
    const int c2 = (lane & 3) * 2;
    const int c4 = (lane & 3) * 4;

    // ---- S = Q K^T : c-frags sf[14][4]; 2 k16 steps over HDIM=32 ----
    float sf[14][4];
    #pragma unroll
    for (int nt = 0; nt < 14; nt++)
        #pragma unroll
        for (int r = 0; r < 4; r++) sf[nt][r] = 0.f;

    #pragma unroll
    for (int ks = 0; ks < 2; ks++) {
        const int kb = ks * 16 + c4;
        const __half* ap = sQ + (w8 * 16 + g) * QSTRH + kb;
        uint2 lo = *(const uint2*)ap;
        uint2 hi = *(const uint2*)(ap + 8 * QSTRH);
        uint32_t af[4];
        af[0] = lo.x;
        af[1] = hi.x;
        af[2] = lo.y;
        af[3] = hi.y;
        #pragma unroll
        for (int nt = 0; nt < 14; nt++) {
            const __half* bp = sK + (nt * 8 + g) * KSTRH + kb;
            uint2 bb = *(const uint2*)bp;
            uint32_t bf[2] = { bb.x, bb.y };
            mma_f16(sf[nt], af, bf);
        }
    }

    // ---- bm now needed: wait for group 1 ----
    cp_wait<0>();
    __syncthreads();

    // ---- scale + bias/mask (smem) + row max ----
    const float scale = 0.17677669529663687f;  // 32^-0.5
    float mx[2] = { -1e30f, -1e30f };
    {
        int r0 = w8 * 16 + g;
        int r0c = min(r0, NTOK - 1);
        int r1c = min(r0 + 8, NTOK - 1);
        const float* bm0 = sBM + r0c * BMSTR;
        const float* bm1 = sBM + r1c * BMSTR;
        #pragma unroll
        for (int nt = 0; nt < 14; nt++) {
            int col = nt * 8 + c2;
            float2 b0 = *(const float2*)&bm0[col];
            float2 b1 = *(const float2*)&bm1[col];
            sf[nt][0] = fmaf(sf[nt][0], scale, b0.x);
            sf[nt][1] = fmaf(sf[nt][1], scale, b0.y);
            sf[nt][2] = fmaf(sf[nt][2], scale, b1.x);
            sf[nt][3] = fmaf(sf[nt][3], scale, b1.y);
            mx[0] = fmaxf(mx[0], fmaxf(sf[nt][0], sf[nt][1]));
            mx[1] = fmaxf(mx[1], fmaxf(sf[nt][2], sf[nt][3]));
        }
    }
    #pragma unroll
    for (int hf = 0; hf < 2; hf++) {
        float v = mx[hf];
        v = fmaxf(v, __shfl_xor_sync(0xffffffffu, v, 1));
        v = fmaxf(v, __shfl_xor_sync(0xffffffffu, v, 2));
        mx[hf] = v;
    }

    // ---- exp + row sum ----
    float sum[2] = { 0.f, 0.f };
    #pragma unroll
    for (int nt = 0; nt < 14; nt++) {
        float p0 = __expf(sf[nt][0] - mx[0]);
        float p1 = __expf(sf[nt][1] - mx[0]);
        float p2 = __expf(sf[nt][2] - mx[1]);
        float p3 = __expf(sf[nt][3] - mx[1]);
        sf[nt][0] = p0; sf[nt][1] = p1;
        sf[nt][2] = p2; sf[nt][3] = p3;
        sum[0] += p0 + p1;
        sum[1] += p2 + p3;
    }
    #pragma unroll
    for (int hf = 0; hf < 2; hf++) {
        float v = sum[hf];
        v += __shfl_xor_sync(0xffffffffu, v, 1);
        v += __shfl_xor_sync(0xffffffffu, v, 2);
        sum[hf] = v;
    }

    // ---- O = P V : a-frag = half2 packs of P; b-frag = ldmatrix.x2.trans ----
    float of[4][4];
    #pragma unroll
    for (int nt = 0; nt < 4; nt++)
        #pragma unroll
        for (int r = 0; r < 4; r++) of[nt][r] = 0.f;

    // per-lane ldmatrix base: row = token (lane&15), col 0
    const uint32_t vrow = uV + (uint32_t)((lane & 15) * VSTRH) * 2;

    #pragma unroll
    for (int kt = 0; kt < 7; kt++) {          // 7 k16 steps over 112 tokens
        uint32_t pa[4];
        pa[0] = pack_h2(sf[2*kt][0],   sf[2*kt][1]);
        pa[1] = pack_h2(sf[2*kt][2],   sf[2*kt][3]);
        pa[2] = pack_h2(sf[2*kt+1][0], sf[2*kt+1][1]);
        pa[3] = pack_h2(sf[2*kt+1][2], sf[2*kt+1][3]);
        const uint32_t vkt = vrow + (uint32_t)(kt * 16 * VSTRH) * 2;
        #pragma unroll
        for (int nt = 0; nt < 4; nt++) {
            uint32_t bf[2];
            ldsm_x2_trans(bf[0], bf[1], vkt + nt * 16);
            mma_f16(of[nt], pa, bf);
        }
    }

    // ---- epilogue: normalize, store fp16 for proj ----
    #pragma unroll
    for (int hf = 0; hf < 2; hf++) {
        int row = w8 * 16 + g + hf * 8;
        if (row < NTOK) {
            float inv = 1.f / sum[hf];
            __half* op = d_attnout + ((size_t)b * NTOK + row) * EMB + h * HDIM;
            #pragma unroll
            for (int nt = 0; nt < 4; nt++) {
                int col = nt * 8 + c2;
                uint32_t hv = pack_h2(of[nt][hf * 2 + 0] * inv,
                                      of[nt][hf * 2 + 1] * inv);
                *(uint32_t*)&op[col] = hv;
            }
        }
    }
}

// ---------------------------------------------------------------------------
// Launch
// ---------------------------------------------------------------------------
extern "C" void kernel_launch(void* const* d_in, const int* in_sizes, int n_in,
                              void* d_out, int out_size) {
    const float* x          = (const float*)d_in[0];
    const float* mask       = (const float*)d_in[1];
    const float* qkv_w      = (const float*)d_in[2];
    const float* qkv_b      = (const float*)d_in[3];
    const float* o_w        = (const float*)d_in[4];
    const float* o_b        = (const float*)d_in[5];
    const float* bias_table = (const float*)d_in[6];
    const int*   rel_index  = (const int*)d_in[7];
    float* out = (float*)d_out;

    cudaFuncSetAttribute(gemm_qkv_kernel,
        cudaFuncAttributeMaxDynamicSharedMemorySize, GEMM_SMEM_BYTES);
    cudaFuncSetAttribute(gemm_proj_kernel,
        cudaFuncAttributeMaxDynamicSharedMemorySize, GEMM_SMEM_BYTES);
    cudaFuncSetAttribute(attn_kernel,
        cudaFuncAttributeMaxDynamicSharedMemorySize, ATTN_SMEM_BYTES);

    // pre-conversion + bias/mask combine
    cvt_all_kernel<<<9472, 256>>>(x, qkv_w, o_w);
    combine_bias_kernel<<<dim3((NNP + 255) / 256, NHEADS, NWIN), 256>>>(
        bias_table, rel_index, mask);

    // QKV: M = 200704 (784 tiles of 256), Ncols = 576 (9 tiles of 64)
    gemm_qkv_kernel<<<dim3(9, 784), 256, GEMM_SMEM_BYTES>>>(qkv_b);

    // Attention: one CTA (8 warps) per (b, h)
    attn_kernel<<<BATCH * NHEADS, ATHREADS, ATTN_SMEM_BYTES>>>();

    // Projection: Ncols = 192 (3 tiles of 64)
    gemm_proj_kernel<<<dim3(3, 784), 256, GEMM_SMEM_BYTES>>>(o_b, out);
}